// round 1
// baseline (speedup 1.0000x reference)
#include <cuda_runtime.h>

// MultiClassDiceScore: three 5-bin histograms over 33.5M voxels + tiny epilogue.
// HBM-bound: 268 MB streamed once.

#define NC 5
#define DICE_EPS 1e-7f

// scratch: [0..4]=den1 (pred hist), [5..9]=den2 (mask hist), [10..14]=num (agree hist)
__device__ unsigned int g_hist[16];

__global__ void dice_zero_kernel() {
    if (threadIdx.x < 16) g_hist[threadIdx.x] = 0u;
}

__global__ __launch_bounds__(256, 8)
void dice_hist_kernel(const float4* __restrict__ pred4,
                      const int4* __restrict__ mask4,
                      int nvec) {
    // Packed per-thread histograms: 5 classes x 12-bit slots in a 64-bit acc.
    // Max per-thread elements = ceil(8388608/303104)*4 = 112 << 4095, no overflow.
    unsigned long long accP = 0ull;  // hist of predicted class
    unsigned long long accM = 0ull;  // hist of mask class
    unsigned long long accN = 0ull;  // hist of agreement (pred==mask==c)

    int stride = gridDim.x * blockDim.x;
    for (int i = blockIdx.x * blockDim.x + threadIdx.x; i < nvec; i += stride) {
        float4 p4 = __ldcs(&pred4[i]);
        int4   m4 = __ldcs(&mask4[i]);

        float pf[4] = {p4.x, p4.y, p4.z, p4.w};
        int   mv[4] = {m4.x, m4.y, m4.z, m4.w};

#pragma unroll
        for (int k = 0; k < 4; k++) {
            // p in {0.0..4.0} exactly. p+8 in {8..12}: exponent-field trick
            // extracts the integer value with FADD+SHF+LOP3 (no F2I).
            unsigned int pi = (__float_as_uint(pf[k] + 8.0f) >> 20) & 0xFu;
            unsigned int mi = (unsigned int)mv[k];

            unsigned long long incP = 1ull << (pi * 12u);
            accP += incP;
            accM += 1ull << (mi * 12u);
            if (pi == mi) accN += incP;
        }
    }

    // Unpack 12-bit slots, warp-reduce (REDUX), lane0 -> global integer atomics.
#pragma unroll
    for (int c = 0; c < NC; c++) {
        unsigned int vP = (unsigned int)((accP >> (c * 12)) & 0xFFFull);
        unsigned int vM = (unsigned int)((accM >> (c * 12)) & 0xFFFull);
        unsigned int vN = (unsigned int)((accN >> (c * 12)) & 0xFFFull);
        vP = __reduce_add_sync(0xFFFFFFFFu, vP);
        vM = __reduce_add_sync(0xFFFFFFFFu, vM);
        vN = __reduce_add_sync(0xFFFFFFFFu, vN);
        if ((threadIdx.x & 31) == 0) {
            atomicAdd(&g_hist[c], vP);
            atomicAdd(&g_hist[NC + c], vM);
            atomicAdd(&g_hist[2 * NC + c], vN);
        }
    }
}

__global__ void dice_finalize_kernel(float* __restrict__ out) {
    if (threadIdx.x == 0) {
        float s = 0.0f;
        for (int c = 0; c < NC; c++) {
            float den1 = (float)g_hist[c];
            float den2 = (float)g_hist[NC + c];
            float num  = (float)g_hist[2 * NC + c];
            s += 2.0f * ((num + DICE_EPS) / (den1 + den2 + DICE_EPS));
        }
        out[0] = s / (float)NC;
    }
}

extern "C" void kernel_launch(void* const* d_in, const int* in_sizes, int n_in,
                              void* d_out, int out_size) {
    const float* pred = (const float*)d_in[0];  // output: [128,1,512,512] f32
    const int*   mask = (const int*)d_in[1];    // mask:   [1,128,512,512] i32
    int n = in_sizes[0];       // 33554432, divisible by 4
    int nvec = n >> 2;

    dice_zero_kernel<<<1, 32>>>();
    dice_hist_kernel<<<1184, 256>>>((const float4*)pred, (const int4*)mask, nvec);
    dice_finalize_kernel<<<1, 32>>>((float*)d_out);
}

// round 2
// speedup vs baseline: 2.8803x; 2.8803x over previous
#include <cuda_runtime.h>

// MultiClassDiceScore: 3x 5-bin histograms over 33.5M voxels, SIMD nibble/PRMT
// formulation. Memory-bound target: 268 MB streamed once (~34us floor).
//
// g_hist layout: [0..3]=pred cnt c0..3, [4..7]=mask cnt c0..3,
//                [8..11]=agree cnt c0..3, [12]=total agreements.
// Class-4 bins are derived in the finalize kernel. finalize re-zeroes g_hist
// so every launch (incl. graph replays) starts from zero deterministically.

#define DICE_EPS 1e-7f

__device__ unsigned int g_hist[16];   // zero-initialized at module load

__device__ __forceinline__ unsigned int prmt(unsigned int a, unsigned int b, unsigned int s) {
    unsigned int d;
    asm("prmt.b32 %0, %1, %2, %3;" : "=r"(d) : "r"(a), "r"(b), "r"(s));
    return d;
}

__device__ __forceinline__ unsigned long long addf32x2(unsigned long long a, unsigned long long b) {
    unsigned long long d;
    asm("add.rn.f32x2 %0, %1, %2;" : "=l"(d) : "l"(a), "l"(b));
    return d;
}

// Pack constants: lo half adds 2^23 (label -> bits[0:4)), hi half adds 2^19
// (label -> bits[4:8)), etc. All sums exact in fp32 for labels 0..4.
#define C01 0x490000004B000000ull   // {2^23, 2^19}
#define C23 0x4500000047000000ull   // {2^15, 2^11}

__global__ __launch_bounds__(256, 5)
void dice_main_kernel(const ulonglong2* __restrict__ pred2,
                      const int4* __restrict__ mask4,
                      int nvec) {
    // Byte-lane accumulators: byte k of aX counts elements at lane k of each
    // 4-element group. Max per-thread groups ~45 << 255: no overflow.
    unsigned int aP0 = 0, aP1 = 0, aP2 = 0, aP3 = 0;
    unsigned int aM0 = 0, aM1 = 0, aM2 = 0, aM3 = 0;
    unsigned int aN0 = 0, aN1 = 0, aN2 = 0, aN3 = 0;
    unsigned int aZ  = 0;

    const int stride = gridDim.x * blockDim.x;
    int i = blockIdx.x * blockDim.x + threadIdx.x;

#pragma unroll 2
    for (; i < nvec; i += stride) {
        ulonglong2 p = __ldcs(&pred2[i]);   // 4 float labels
        int4       m = __ldcs(&mask4[i]);   // 4 int labels

        // selP nibbles = [p0,p1,p2,p3] via packed-f32 exponent trick.
        unsigned long long a01 = addf32x2(p.x, C01);
        unsigned long long a23 = addf32x2(p.y, C23);
        unsigned int selP = (unsigned int)a01 | (unsigned int)(a01 >> 32)
                          | (unsigned int)a23 | (unsigned int)(a23 >> 32);
        // selM nibbles = [m0,m1,m2,m3]
        unsigned int selM = (unsigned int)m.x + ((unsigned int)m.y << 4)
                          + ((unsigned int)m.z << 8) + ((unsigned int)m.w << 12);

        // zd byte k = 1 iff p_k == m_k  (nibble-zero detect, one PRMT LUT)
        unsigned int agr = selP ^ selM;           // nibbles in [0,7]
        unsigned int zd  = prmt(0x00000001u, 0u, agr);
        aZ += zd;

        // per-class equality bytes via PRMT LUTs (classes 0..3; 4 derived)
        unsigned int eP0 = prmt(0x00000001u, 0u, selP);
        unsigned int eP1 = prmt(0x00000100u, 0u, selP);
        unsigned int eP2 = prmt(0x00010000u, 0u, selP);
        unsigned int eP3 = prmt(0x01000000u, 0u, selP);
        aP0 += eP0; aP1 += eP1; aP2 += eP2; aP3 += eP3;

        unsigned int eM0 = prmt(0x00000001u, 0u, selM);
        unsigned int eM1 = prmt(0x00000100u, 0u, selM);
        unsigned int eM2 = prmt(0x00010000u, 0u, selM);
        unsigned int eM3 = prmt(0x01000000u, 0u, selM);
        aM0 += eM0; aM1 += eM1; aM2 += eM2; aM3 += eM3;

        aN0 += eP0 & zd; aN1 += eP1 & zd; aN2 += eP2 & zd; aN3 += eP3 & zd;
    }

    // Horizontal byte sums, warp reduce, block reduce, 13 global atomics/block.
    unsigned int v[13];
    v[0]  = (unsigned int)__dp4a((int)aP0, 0x01010101, 0);
    v[1]  = (unsigned int)__dp4a((int)aP1, 0x01010101, 0);
    v[2]  = (unsigned int)__dp4a((int)aP2, 0x01010101, 0);
    v[3]  = (unsigned int)__dp4a((int)aP3, 0x01010101, 0);
    v[4]  = (unsigned int)__dp4a((int)aM0, 0x01010101, 0);
    v[5]  = (unsigned int)__dp4a((int)aM1, 0x01010101, 0);
    v[6]  = (unsigned int)__dp4a((int)aM2, 0x01010101, 0);
    v[7]  = (unsigned int)__dp4a((int)aM3, 0x01010101, 0);
    v[8]  = (unsigned int)__dp4a((int)aN0, 0x01010101, 0);
    v[9]  = (unsigned int)__dp4a((int)aN1, 0x01010101, 0);
    v[10] = (unsigned int)__dp4a((int)aN2, 0x01010101, 0);
    v[11] = (unsigned int)__dp4a((int)aN3, 0x01010101, 0);
    v[12] = (unsigned int)__dp4a((int)aZ,  0x01010101, 0);

    __shared__ unsigned int sh[13];
    if (threadIdx.x < 13) sh[threadIdx.x] = 0u;
    __syncthreads();

#pragma unroll
    for (int k = 0; k < 13; k++) {
        unsigned int w = __reduce_add_sync(0xFFFFFFFFu, v[k]);
        if ((threadIdx.x & 31) == 0) atomicAdd(&sh[k], w);
    }
    __syncthreads();
    if (threadIdx.x < 13) atomicAdd(&g_hist[threadIdx.x], sh[threadIdx.x]);
}

__global__ void dice_finalize_kernel(float* __restrict__ out, int n_total) {
    if (threadIdx.x == 0) {
        unsigned int P[5], M[5], Nm[5];
        unsigned int sp = 0, sm = 0, sn = 0;
#pragma unroll
        for (int c = 0; c < 4; c++) {
            P[c]  = g_hist[c];       sp += P[c];
            M[c]  = g_hist[4 + c];   sm += M[c];
            Nm[c] = g_hist[8 + c];   sn += Nm[c];
        }
        unsigned int Z = g_hist[12];
        P[4]  = (unsigned int)n_total - sp;
        M[4]  = (unsigned int)n_total - sm;
        Nm[4] = Z - sn;

        float s = 0.0f;
#pragma unroll
        for (int c = 0; c < 5; c++) {
            float den1 = (float)P[c];
            float den2 = (float)M[c];
            float num  = (float)Nm[c];
            s += 2.0f * ((num + DICE_EPS) / (den1 + den2 + DICE_EPS));
        }
        out[0] = s * 0.2f;

        // leave state zeroed for the next (graph-replayed) launch
#pragma unroll
        for (int k = 0; k < 16; k++) g_hist[k] = 0u;
    }
}

extern "C" void kernel_launch(void* const* d_in, const int* in_sizes, int n_in,
                              void* d_out, int out_size) {
    const float* pred = (const float*)d_in[0];  // [128,1,512,512] f32, values 0..4
    const int*   mask = (const int*)d_in[1];    // [1,128,512,512] i32, values 0..4
    int n = in_sizes[0];                        // 33,554,432 (divisible by 4)
    int nvec = n >> 2;

    dice_main_kernel<<<740, 256>>>((const ulonglong2*)pred, (const int4*)mask, nvec);
    dice_finalize_kernel<<<1, 32>>>((float*)d_out, n);
}